// round 14
// baseline (speedup 1.0000x reference)
#include <cuda_runtime.h>
#include <math.h>

#define BB 32
#define TT 256
#define FF 2048
#define KK 16
#define NCC 10
#define SLICES 4        // CTAs per row
#define NTHR 128        // 4 warps
#define NL1 16          // level-1 arrival counters (16 CTAs each)

__device__ float g_part[2 * BB][SLICES];   // [row][slice], 16B contiguous per row
__device__ float g_bce[2 * BB];            // finished BCE terms, concat order
__device__ unsigned int g_cnt1[NL1][32];   // 128B stride -> distinct LTS addresses
__device__ unsigned int g_cnt2 = 0;

__device__ __forceinline__ unsigned int atom_add_acqrel(unsigned int* p) {
    unsigned int r;
    asm volatile("atom.acq_rel.gpu.global.add.u32 %0, [%1], 1;"
                 : "=r"(r) : "l"(p) : "memory");
    return r;
}

__device__ __forceinline__ float4 ldcg_f4(const float4* p) {
    float4 r;
    asm volatile("ld.global.cg.v4.f32 {%0,%1,%2,%3}, [%4];"
                 : "=f"(r.x), "=f"(r.y), "=f"(r.z), "=f"(r.w) : "l"(p));
    return r;
}

__global__ void fused_kernel(
    const float* __restrict__ abn_fm,
    const float* __restrict__ nor_fm,
    const float* __restrict__ abn_ft,
    const float* __restrict__ nor_ft,
    const float* __restrict__ abn_sls,
    const float* __restrict__ nor_sls,
    const float* __restrict__ abn_dm,
    const float* __restrict__ nor_dm,
    const float* __restrict__ label,
    float* __restrict__ out)
{
    const int bid   = blockIdx.x;          // 0..255
    const int row   = bid >> 2;            // 0..63
    const int slice = bid & (SLICES - 1);  // 0..3
    const int b     = row & (BB - 1);
    const bool is_abn = (row < BB);

    const float* fm  = is_abn ? abn_fm  : nor_fm;
    const float* dm  = is_abn ? abn_dm  : nor_dm;
    const float* sls = is_abn ? abn_sls : nor_sls;
    const float* ft  = (is_abn ? abn_ft : nor_ft)
                     + (size_t)(NCC - 1) * BB * TT * FF + (size_t)b * TT * FF;

    const int tid  = threadIdx.x;
    const int wid  = tid >> 5;
    const int lane = tid & 31;
    const bool vls_warp = (slice == 0 && wid == 0);
    // vls = concat([vls_norm, vls_abn]): abn row b -> slot BB+b, norm row b -> slot b
    const int lidx = is_abn ? (BB + b) : b;

    // ---- chain-gating loads FIRST: fm/dm (vectorized) ----
    // slot j<4 : t = 4*lane + j ; slot j>=4 : t = 128 + 4*lane + (j-4)
    const float4* fm4 = (const float4*)(fm + b * TT);
    const float4* dm4 = (const float4*)(dm + b * TT);
    float4 fa = fm4[lane],      da = dm4[lane];
    float4 fb = fm4[32 + lane], db = dm4[32 + lane];

    // ---- then sls row + label prefetch (vls warp; overlaps top-K) ----
    float sv[8];
    float lab = 0.0f;
    if (vls_warp) {
        const float4* s4 = (const float4*)(sls + b * TT);
        float4 sa = s4[lane];        // t = 4l .. 4l+3
        float4 sb = s4[32 + lane];   // t = 128+4l ..
        sv[0] = sa.x; sv[1] = sa.y; sv[2] = sa.z; sv[3] = sa.w;
        sv[4] = sb.x; sv[5] = sb.y; sv[6] = sb.z; sv[7] = sb.w;
        if (lane == 0) lab = label[lidx];
    }

    // ---- keys: top24(float bits) | (255 - t) ----
    unsigned int key[8];
    {
        int t0 = 4 * lane;
        key[0] = (__float_as_uint(fa.x * da.x) & 0xFFFFFF00u) | (255u - (unsigned)(t0 + 0));
        key[1] = (__float_as_uint(fa.y * da.y) & 0xFFFFFF00u) | (255u - (unsigned)(t0 + 1));
        key[2] = (__float_as_uint(fa.z * da.z) & 0xFFFFFF00u) | (255u - (unsigned)(t0 + 2));
        key[3] = (__float_as_uint(fa.w * da.w) & 0xFFFFFF00u) | (255u - (unsigned)(t0 + 3));
        key[4] = (__float_as_uint(fb.x * db.x) & 0xFFFFFF00u) | (255u - (unsigned)(t0 + 128));
        key[5] = (__float_as_uint(fb.y * db.y) & 0xFFFFFF00u) | (255u - (unsigned)(t0 + 129));
        key[6] = (__float_as_uint(fb.z * db.z) & 0xFFFFFF00u) | (255u - (unsigned)(t0 + 130));
        key[7] = (__float_as_uint(fb.w * db.w) & 0xFFFFFF00u) | (255u - (unsigned)(t0 + 131));
    }

    // ---- per-lane top-2 seed (branch-free) ----
    unsigned int l1 = 0u, l2 = 0u;
    #pragma unroll
    for (int j = 0; j < 8; j++) {
        unsigned int kj = key[j];
        unsigned int nl1 = max(l1, kj);
        l2 = max(l2, min(l1, kj));
        l1 = nl1;
    }

    // ---- per-warp redundant top-16: chain = REDUX -> compare/select.
    //      l2 refill uniform + branch-free. Gather loads issued per round,
    //      consumed after the loop. ----
    const float4* ft4 = (const float4*)ft;
    const int f4 = slice * (FF / 4 / SLICES) + tid;   // 128 float4 per slice
    float4 v[KK];
    unsigned int myidx = 0;      // lane k holds selected index of round k

    #pragma unroll
    for (int k = 0; k < KK; k++) {
        unsigned int m = __reduce_max_sync(0xFFFFFFFFu, l1);
        unsigned int cand = 255u - (m & 0xFFu);   // uniform across warp
        if (lane == k) myidx = cand;
        v[k] = ft4[(size_t)cand * (FF / 4) + f4]; // issue, don't consume

        #pragma unroll
        for (int j = 0; j < 8; j++)
            key[j] = (key[j] == m) ? 0u : key[j];
        l1 = (l1 == m) ? l2 : l1;                 // chain-critical select
        unsigned int nm = 0u;                     // off-chain l2 refill
        #pragma unroll
        for (int j = 0; j < 8; j++) {
            unsigned int kj = key[j];
            nm = max(nm, (kj == l1) ? 0u : kj);
        }
        l2 = nm;
    }

    // ---- vls mean + BCE term (hidden under gather drain) ----
    if (vls_warp) {
        int tt   = (int)myidx;
        int src  = (tt & 127) >> 2;
        int slot = (tt & 3) + ((tt >> 7) << 2);
        float val = 0.0f;
        #pragma unroll
        for (int j = 0; j < 8; j++) {
            float t = __shfl_sync(0xFFFFFFFFu, sv[j], src);
            if (j == slot) val = t;
        }
        if (lane >= KK) val = 0.0f;
        #pragma unroll
        for (int off = 16; off > 0; off >>= 1)
            val += __shfl_xor_sync(0xFFFFFFFFu, val, off);
        if (lane == 0) {
            float p = val * (1.0f / KK);
            float logp   = fmaxf(logf(p),    -100.0f);
            float log1mp = fmaxf(log1pf(-p), -100.0f);
            g_bce[lidx] = lab * logp + (1.0f - lab) * log1mp;
        }
    }

    // ---- deferred accumulation ----
    float4 a0 = make_float4(0.f, 0.f, 0.f, 0.f);
    float4 a1 = make_float4(0.f, 0.f, 0.f, 0.f);
    #pragma unroll
    for (int k = 0; k < KK; k += 2) {
        a0.x += v[k].x;   a0.y += v[k].y;   a0.z += v[k].z;   a0.w += v[k].w;
        a1.x += v[k+1].x; a1.y += v[k+1].y; a1.z += v[k+1].z; a1.w += v[k+1].w;
    }
    a0.x += a1.x; a0.y += a1.y; a0.z += a1.z; a0.w += a1.w;
    float local = a0.x * a0.x + a0.y * a0.y + a0.z * a0.z + a0.w * a0.w;

    // ---- block reduce -> partial sum of squares ----
    __shared__ float swarp[4];
    __shared__ unsigned int s_last;
    #pragma unroll
    for (int off = 16; off > 0; off >>= 1)
        local += __shfl_xor_sync(0xFFFFFFFFu, local, off);
    if (lane == 0) swarp[wid] = local;
    __syncthreads();

    // ---- balanced two-level arrival tree (16x16 -> 16), acq_rel ordering ----
    if (tid == 0) {
        float tot = swarp[0] + swarp[1] + swarp[2] + swarp[3];
        g_part[row][slice] = tot;                 // ordered by release in atomic
        unsigned int last = 0;
        unsigned int r1 = atom_add_acqrel(&g_cnt1[bid >> 4][0]);  // 16 CTAs each
        if (r1 == 15u) {
            unsigned int r2 = atom_add_acqrel(&g_cnt2);
            last = (r2 == NL1 - 1u) ? 1u : 0u;
        }
        s_last = last;
    }
    __syncthreads();

    // ---- last block finalizes: single warp, no barriers ----
    if (s_last) {
        if (wid == 0) {
            // BCE: lane covers concat slots lane and lane+32
            float bce = __ldcg(&g_bce[lane]) + __ldcg(&g_bce[32 + lane]);
            // RTFM: lane covers pair b = lane
            float4 pa = ldcg_f4((const float4*)&g_part[lane][0]);
            float4 pn = ldcg_f4((const float4*)&g_part[BB + lane][0]);
            float sa = pa.x + pa.y + pa.z + pa.w;
            float sn = pn.x + pn.y + pn.z + pn.w;
            float la = fabsf(100.0f - sqrtf(sa) * (1.0f / KK));
            float ln = sqrtf(sn) * (1.0f / KK);
            float l  = la + ln;
            float rt = l * l;
            #pragma unroll
            for (int off = 16; off > 0; off >>= 1) {
                rt  += __shfl_xor_sync(0xFFFFFFFFu, rt,  off);
                bce += __shfl_xor_sync(0xFFFFFFFFu, bce, off);
            }
            if (lane == 0) {
                out[0] = 1e-4f * (rt * (1.0f / BB));
                out[1] = -bce * (1.0f / 64.0f);
            }
        } else if (wid == 1) {
            // reset arrival counters for next graph replay (independent of out)
            if (lane < NL1) g_cnt1[lane][0] = 0u;
            if (lane == NL1) g_cnt2 = 0u;
        }
    }
}

extern "C" void kernel_launch(void* const* d_in, const int* in_sizes, int n_in,
                              void* d_out, int out_size)
{
    const float* abnr_fmagn = (const float*)d_in[0];
    const float* norm_fmagn = (const float*)d_in[1];
    const float* abnr_feats = (const float*)d_in[2];
    const float* norm_feats = (const float*)d_in[3];
    const float* abnr_sls   = (const float*)d_in[4];
    const float* norm_sls   = (const float*)d_in[5];
    const float* label      = (const float*)d_in[6];
    const float* drop_abn   = (const float*)d_in[7];
    const float* drop_norm  = (const float*)d_in[8];

    fused_kernel<<<2 * BB * SLICES, NTHR>>>(abnr_fmagn, norm_fmagn,
                                            abnr_feats, norm_feats,
                                            abnr_sls, norm_sls,
                                            drop_abn, drop_norm,
                                            label, (float*)d_out);
}

// round 15
// speedup vs baseline: 1.1397x; 1.1397x over previous
#include <cuda_runtime.h>
#include <math.h>

#define BB 32
#define TT 256
#define FF 2048
#define KK 16
#define NCC 10
#define SLICES 4        // CTAs per row
#define NTHR 128        // 4 warps
#define NL1 32          // level-1 arrival counters (8 CTAs each)

__device__ float g_part[2 * BB][SLICES];   // [row][slice], 16B contiguous per row
__device__ float g_bce[2 * BB];            // finished BCE terms, concat order
__device__ unsigned int g_cnt1[NL1][32];   // 128B stride -> distinct LTS addresses
__device__ unsigned int g_cnt2 = 0;

__device__ __forceinline__ unsigned int atom_add_acqrel(unsigned int* p) {
    unsigned int r;
    asm volatile("atom.acq_rel.gpu.global.add.u32 %0, [%1], 1;"
                 : "=r"(r) : "l"(p) : "memory");
    return r;
}

__device__ __forceinline__ float4 ldcg_f4(const float4* p) {
    float4 r;
    asm volatile("ld.global.cg.v4.f32 {%0,%1,%2,%3}, [%4];"
                 : "=f"(r.x), "=f"(r.y), "=f"(r.z), "=f"(r.w) : "l"(p));
    return r;
}

__global__ void fused_kernel(
    const float* __restrict__ abn_fm,
    const float* __restrict__ nor_fm,
    const float* __restrict__ abn_ft,
    const float* __restrict__ nor_ft,
    const float* __restrict__ abn_sls,
    const float* __restrict__ nor_sls,
    const float* __restrict__ abn_dm,
    const float* __restrict__ nor_dm,
    const float* __restrict__ label,
    float* __restrict__ out)
{
    const int bid   = blockIdx.x;          // 0..255
    const int row   = bid >> 2;            // 0..63
    const int slice = bid & (SLICES - 1);  // 0..3
    const int b     = row & (BB - 1);
    const bool is_abn = (row < BB);

    const float* fm  = is_abn ? abn_fm  : nor_fm;
    const float* dm  = is_abn ? abn_dm  : nor_dm;
    const float* sls = is_abn ? abn_sls : nor_sls;
    const float* ft  = (is_abn ? abn_ft : nor_ft)
                     + (size_t)(NCC - 1) * BB * TT * FF + (size_t)b * TT * FF;

    const int tid  = threadIdx.x;
    const int wid  = tid >> 5;
    const int lane = tid & 31;
    const bool vls_warp = (slice == 0 && wid == 0);
    // vls = concat([vls_norm, vls_abn]): abn row b -> slot BB+b, norm row b -> slot b
    const int lidx = is_abn ? (BB + b) : b;

    // ---- vectorized prefetch: sls row + label (vls warp; overlaps top-K) ----
    float sv[8];
    float lab = 0.0f;
    if (vls_warp) {
        const float4* s4 = (const float4*)(sls + b * TT);
        float4 sa = s4[lane];        // t = 4l .. 4l+3
        float4 sb = s4[32 + lane];   // t = 128+4l ..
        sv[0] = sa.x; sv[1] = sa.y; sv[2] = sa.z; sv[3] = sa.w;
        sv[4] = sb.x; sv[5] = sb.y; sv[6] = sb.z; sv[7] = sb.w;
        if (lane == 0) lab = label[lidx];
    }

    // ---- vectorized drop values; key = top24(float bits) | (255 - t) ----
    // slot j<4 : t = 4*lane + j ; slot j>=4 : t = 128 + 4*lane + (j-4)
    unsigned int key[8];
    {
        const float4* fm4 = (const float4*)(fm + b * TT);
        const float4* dm4 = (const float4*)(dm + b * TT);
        float4 fa = fm4[lane],      da = dm4[lane];
        float4 fb = fm4[32 + lane], db = dm4[32 + lane];
        int t0 = 4 * lane;
        key[0] = (__float_as_uint(fa.x * da.x) & 0xFFFFFF00u) | (255u - (unsigned)(t0 + 0));
        key[1] = (__float_as_uint(fa.y * da.y) & 0xFFFFFF00u) | (255u - (unsigned)(t0 + 1));
        key[2] = (__float_as_uint(fa.z * da.z) & 0xFFFFFF00u) | (255u - (unsigned)(t0 + 2));
        key[3] = (__float_as_uint(fa.w * da.w) & 0xFFFFFF00u) | (255u - (unsigned)(t0 + 3));
        key[4] = (__float_as_uint(fb.x * db.x) & 0xFFFFFF00u) | (255u - (unsigned)(t0 + 128));
        key[5] = (__float_as_uint(fb.y * db.y) & 0xFFFFFF00u) | (255u - (unsigned)(t0 + 129));
        key[6] = (__float_as_uint(fb.z * db.z) & 0xFFFFFF00u) | (255u - (unsigned)(t0 + 130));
        key[7] = (__float_as_uint(fb.w * db.w) & 0xFFFFFF00u) | (255u - (unsigned)(t0 + 131));
    }

    // ---- per-lane top-2 seed (branch-free) ----
    unsigned int l1 = 0u, l2 = 0u;
    #pragma unroll
    for (int j = 0; j < 8; j++) {
        unsigned int kj = key[j];
        unsigned int nl1 = max(l1, kj);
        l2 = max(l2, min(l1, kj));
        l1 = nl1;
    }

    // ---- per-warp redundant top-16: chain = REDUX -> compare/select.
    //      l2 refill is uniform + branch-free (non-owners recompute l2
    //      unchanged; owner gets its 3rd best). All SEL/MAX, no BSSY. ----
    const float4* ft4 = (const float4*)ft;
    const int f4 = slice * (FF / 4 / SLICES) + tid;   // 128 float4 per slice
    float4 v[KK];
    unsigned int myidx = 0;      // lane k holds selected index of round k

    #pragma unroll
    for (int k = 0; k < KK; k++) {
        unsigned int m = __reduce_max_sync(0xFFFFFFFFu, l1);
        unsigned int cand = 255u - (m & 0xFFu);   // uniform across warp
        if (lane == k) myidx = cand;
        v[k] = ft4[(size_t)cand * (FF / 4) + f4]; // issue, don't consume

        // clear winner (only owner lane holds it; executing everywhere is free)
        #pragma unroll
        for (int j = 0; j < 8; j++)
            key[j] = (key[j] == m) ? 0u : key[j];
        // advance l1 (chain-critical: one compare + one select)
        l1 = (l1 == m) ? l2 : l1;
        // refill l2 = max over keys != l1 (off the critical chain)
        unsigned int nm = 0u;
        #pragma unroll
        for (int j = 0; j < 8; j++) {
            unsigned int kj = key[j];
            nm = max(nm, (kj == l1) ? 0u : kj);
        }
        l2 = nm;
    }

    // ---- vls mean + BCE term (hidden under gather drain) ----
    if (vls_warp) {
        int tt   = (int)myidx;
        int src  = (tt & 127) >> 2;
        int slot = (tt & 3) + ((tt >> 7) << 2);
        float val = 0.0f;
        #pragma unroll
        for (int j = 0; j < 8; j++) {
            float t = __shfl_sync(0xFFFFFFFFu, sv[j], src);
            if (j == slot) val = t;
        }
        if (lane >= KK) val = 0.0f;
        #pragma unroll
        for (int off = 16; off > 0; off >>= 1)
            val += __shfl_xor_sync(0xFFFFFFFFu, val, off);
        if (lane == 0) {
            float p = val * (1.0f / KK);
            float logp   = fmaxf(logf(p),    -100.0f);
            float log1mp = fmaxf(log1pf(-p), -100.0f);
            g_bce[lidx] = lab * logp + (1.0f - lab) * log1mp;
        }
    }

    // ---- deferred accumulation ----
    float4 a0 = make_float4(0.f, 0.f, 0.f, 0.f);
    float4 a1 = make_float4(0.f, 0.f, 0.f, 0.f);
    #pragma unroll
    for (int k = 0; k < KK; k += 2) {
        a0.x += v[k].x;   a0.y += v[k].y;   a0.z += v[k].z;   a0.w += v[k].w;
        a1.x += v[k+1].x; a1.y += v[k+1].y; a1.z += v[k+1].z; a1.w += v[k+1].w;
    }
    a0.x += a1.x; a0.y += a1.y; a0.z += a1.z; a0.w += a1.w;
    float local = a0.x * a0.x + a0.y * a0.y + a0.z * a0.z + a0.w * a0.w;

    // ---- block reduce -> partial sum of squares ----
    __shared__ float swarp[4];
    __shared__ unsigned int s_last;
    #pragma unroll
    for (int off = 16; off > 0; off >>= 1)
        local += __shfl_xor_sync(0xFFFFFFFFu, local, off);
    if (lane == 0) swarp[wid] = local;
    __syncthreads();

    // ---- two-level arrival tree; acq_rel atomics carry the ordering ----
    if (tid == 0) {
        float tot = swarp[0] + swarp[1] + swarp[2] + swarp[3];
        g_part[row][slice] = tot;                 // ordered by release in atomic
        unsigned int last = 0;
        unsigned int r1 = atom_add_acqrel(&g_cnt1[bid >> 3][0]);  // 8 CTAs each
        if (r1 == 7u) {
            unsigned int r2 = atom_add_acqrel(&g_cnt2);
            last = (r2 == NL1 - 1u) ? 1u : 0u;
        }
        s_last = last;
    }
    __syncthreads();

    // ---- last block finalizes (acquire from last arrival orders these reads) ----
    if (s_last) {
        __shared__ float s_rt[2];
        __shared__ float s_bce[2];

        if (tid < 64) {
            float bce = __ldcg(&g_bce[tid]);
            float rt = 0.0f;
            if (tid < BB) {
                float4 pa = ldcg_f4((const float4*)&g_part[tid][0]);
                float4 pn = ldcg_f4((const float4*)&g_part[BB + tid][0]);
                float sa = pa.x + pa.y + pa.z + pa.w;
                float sn = pn.x + pn.y + pn.z + pn.w;
                float la = fabsf(100.0f - sqrtf(sa) * (1.0f / KK));
                float ln = sqrtf(sn) * (1.0f / KK);
                float l = la + ln;
                rt = l * l;
            }
            #pragma unroll
            for (int off = 16; off > 0; off >>= 1) {
                rt  += __shfl_xor_sync(0xFFFFFFFFu, rt,  off);
                bce += __shfl_xor_sync(0xFFFFFFFFu, bce, off);
            }
            if (lane == 0) { s_rt[wid] = rt; s_bce[wid] = bce; }
        }
        // reset arrival counters for next graph replay
        if (tid >= 64 && tid < 64 + NL1) g_cnt1[tid - 64][0] = 0u;
        if (tid == 64 + NL1) g_cnt2 = 0u;
        __syncthreads();
        if (tid == 0) {
            out[0] = 1e-4f * ((s_rt[0] + s_rt[1]) * (1.0f / BB));
            out[1] = -(s_bce[0] + s_bce[1]) * (1.0f / 64.0f);
        }
    }
}

extern "C" void kernel_launch(void* const* d_in, const int* in_sizes, int n_in,
                              void* d_out, int out_size)
{
    const float* abnr_fmagn = (const float*)d_in[0];
    const float* norm_fmagn = (const float*)d_in[1];
    const float* abnr_feats = (const float*)d_in[2];
    const float* norm_feats = (const float*)d_in[3];
    const float* abnr_sls   = (const float*)d_in[4];
    const float* norm_sls   = (const float*)d_in[5];
    const float* label      = (const float*)d_in[6];
    const float* drop_abn   = (const float*)d_in[7];
    const float* drop_norm  = (const float*)d_in[8];

    fused_kernel<<<2 * BB * SLICES, NTHR>>>(abnr_fmagn, norm_fmagn,
                                            abnr_feats, norm_feats,
                                            abnr_sls, norm_sls,
                                            drop_abn, drop_norm,
                                            label, (float*)d_out);
}